// round 16
// baseline (speedup 1.0000x reference)
#include <cuda_runtime.h>
#include <cstdint>

#define RES      64
#define N_PHAL   20
#define MAX_B    256

constexpr int POS_PER_CHUNK = RES * RES;             // 4096 positions per (b,p)
constexpr int F4_PER_CHUNK  = POS_PER_CHUNK * 5 / 4; // 5120 float4s per chunk
constexpr int TILE_POS      = 2048;                  // positions per smem tile
constexpr int TILE_F4       = TILE_POS * 5 / 4;      // 2560 float4s = 40 KB
constexpr int THREADS       = 256;

// Scratch: per (b,p): vf0, vf1, vs0, vs1, den
__device__ float        g_scratch[MAX_B * N_PHAL * 5];
__device__ unsigned int g_count = 0;

__device__ __forceinline__ float warp_red(float v) {
    #pragma unroll
    for (int o = 16; o > 0; o >>= 1)
        v += __shfl_down_sync(0xffffffffu, v, o);
    return v;
}

// Release add: orders this thread's prior global stores into L2, no L1 flush.
__device__ __forceinline__ unsigned int atom_add_release(unsigned int* p,
                                                         unsigned int v) {
    unsigned int old;
    asm volatile("atom.release.gpu.add.u32 %0, [%1], %2;"
                 : "=r"(old) : "l"(p), "r"(v) : "memory");
    return old;
}
__device__ __forceinline__ unsigned int ld_acquire(unsigned int* p) {
    unsigned int v;
    asm volatile("ld.acquire.gpu.u32 %0, [%1];" : "=r"(v) : "l"(p) : "memory");
    return v;
}

// grid = total_chunks + 1. Blocks [0, total_chunks): R14 reduce engine
// (PROTECTED: R2 schedule + __ldcs). Block total_chunks: trailing waiter that
// assembles the output once every reduce block has released its scratch —
// disjoint code path, so hot-path register allocation is untouched.
__global__ __launch_bounds__(THREADS) void fused_kernel(
    const float4* __restrict__ x, float* __restrict__ scratch,
    float* __restrict__ out, int total_chunks)
{
    const int t = threadIdx.x;

    // ================= waiter path (one block, scheduled last) =============
    if ((int)blockIdx.x == total_chunks) {
        if (t == 0) {
            while (ld_acquire(&g_count) < (unsigned)total_chunks)
                __nanosleep(64);
        }
        __syncthreads();

        const int B = total_chunks / N_PHAL;
        const int total = B * 42;
        for (int o = t; o < total; o += THREADS) {
            int c = o & 1;
            int r = (o >> 1) % 21;
            int b = o / 42;
            const float* sp = scratch + (size_t)b * N_PHAL * 5;

            float val;
            if (r == 0) {
                float acc = 0.f;
                #pragma unroll
                for (int k = 0; k < 5; ++k) {
                    int p = 4 * k;
                    float dn = __ldcg(sp + p * 5 + 4);
                    float vf = __ldcg(sp + p * 5 + c);
                    acc += (dn != 0.f) ? vf : 0.f;
                }
                val = acc * 0.2f;
            } else {
                int q  = r;                  // 1..20
                int iq = (q - 1) >> 2;
                int pq = 8 * iq + 4 - q;     // 4*iq + j_q
                int jq = pq - 4 * iq;
                int pn = min(pq + 1, N_PHAL - 1);
                float vs = __ldcg(sp + pq * 5 + 2 + c);
                if (jq == 3) val = vs;
                else         val = 0.5f * (vs + __ldcg(sp + pn * 5 + c));
            }
            out[o] = val;
        }
        __syncthreads();
        if (t == 0) g_count = 0;     // single waiter: reset is race-free
        return;
    }

    // ================= reduce path (R14 engine, unchanged) =================
    __shared__ float4 tile[TILE_F4];     // 40 KB
    __shared__ float  red[8][7];

    const int chunk = blockIdx.x;        // b * N_PHAL + p
    const float4* base = x + (size_t)chunk * F4_PER_CHUNK;

    float A = 0.f, Bm = 0.f, C = 0.f, D = 0.f, E = 0.f, F = 0.f, den = 0.f;

    #pragma unroll
    for (int it = 0; it < 2; ++it) {
        // ---- coalesced streaming load: 2560 float4s, 10 per thread ----
        #pragma unroll
        for (int k = 0; k < 10; ++k) {
            int idx = k * THREADS + t;
            tile[idx] = __ldcs(base + it * TILE_F4 + idx);   // evict-first
        }
        __syncthreads();

        // ---- deinterleave + accumulate: 2 groups of 4 positions per thread ----
        #pragma unroll
        for (int gs = 0; gs < 2; ++gs) {
            int g = gs * THREADS + t;            // group-of-4 index within tile
            // 5 x LDS.128 at 80B lane stride: conflict-free
            float4 v0 = tile[g * 5 + 0];
            float4 v1 = tile[g * 5 + 1];
            float4 v2 = tile[g * 5 + 2];
            float4 v3 = tile[g * 5 + 3];
            float4 v4 = tile[g * 5 + 4];

            int pos0 = it * TILE_POS + g * 4;    // first global position of group
            float fi  = (float)(pos0 >> 6);      // row (same for all 4: 4 | 64)
            float fj0 = (float)(pos0 & 63);      // first column

            // p0: f0=v0.x f1=v0.y m=v0.z d0=v0.w d1=v1.x
            { float m = v0.z, am = fabsf(m), s = m * am;
              float t0 = s * v0.x, t1 = s * v0.y;
              A  = fmaf(t1, v0.w, A);  Bm = fmaf(t0, v0.w, Bm);
              C  = fmaf(t1, v1.x, C);  D  = fmaf(t0, v1.x, D);
              E  = fmaf(am, fi, E);    F  = fmaf(am, fj0, F);
              den += am; }
            // p1: f0=v1.y f1=v1.z m=v1.w d0=v2.x d1=v2.y
            { float m = v1.w, am = fabsf(m), s = m * am;
              float t0 = s * v1.y, t1 = s * v1.z;
              A  = fmaf(t1, v2.x, A);  Bm = fmaf(t0, v2.x, Bm);
              C  = fmaf(t1, v2.y, C);  D  = fmaf(t0, v2.y, D);
              E  = fmaf(am, fi, E);    F  = fmaf(am, fj0 + 1.f, F);
              den += am; }
            // p2: f0=v2.z f1=v2.w m=v3.x d0=v3.y d1=v3.z
            { float m = v3.x, am = fabsf(m), s = m * am;
              float t0 = s * v2.z, t1 = s * v2.w;
              A  = fmaf(t1, v3.y, A);  Bm = fmaf(t0, v3.y, Bm);
              C  = fmaf(t1, v3.z, C);  D  = fmaf(t0, v3.z, D);
              E  = fmaf(am, fi, E);    F  = fmaf(am, fj0 + 2.f, F);
              den += am; }
            // p3: f0=v3.w f1=v4.x m=v4.y d0=v4.z d1=v4.w
            { float m = v4.y, am = fabsf(m), s = m * am;
              float t0 = s * v3.w, t1 = s * v4.x;
              A  = fmaf(t1, v4.z, A);  Bm = fmaf(t0, v4.z, Bm);
              C  = fmaf(t1, v4.w, C);  D  = fmaf(t0, v4.w, D);
              E  = fmaf(am, fi, E);    F  = fmaf(am, fj0 + 3.f, F);
              den += am; }
        }
        __syncthreads();   // tile reused next iteration
    }

    // ---- block reduction of 7 accumulators ----
    A = warp_red(A);  Bm = warp_red(Bm); C = warp_red(C); D = warp_red(D);
    E = warp_red(E);  F  = warp_red(F);  den = warp_red(den);

    int wid = t >> 5, lane = t & 31;
    if (lane == 0) {
        red[wid][0] = A;  red[wid][1] = Bm; red[wid][2] = C;
        red[wid][3] = D;  red[wid][4] = E;  red[wid][5] = F;
        red[wid][6] = den;
    }
    __syncthreads();

    if (t == 0) {
        float a = 0.f, b = 0.f, c = 0.f, d = 0.f, e = 0.f, f = 0.f, dn = 0.f;
        #pragma unroll
        for (int w = 0; w < 8; ++w) {
            a += red[w][0]; b += red[w][1]; c += red[w][2];
            d += red[w][3]; e += red[w][4]; f += red[w][5];
            dn += red[w][6];
        }
        float inv = 1.f / ((dn == 0.f) ? 1.f : dn);
        float* o = scratch + (size_t)chunk * 5;
        o[0] = (a + e) * inv;   // vf0
        o[1] = (f - b) * inv;   // vf1
        o[2] = (e - c) * inv;   // vs0
        o[3] = (d + f) * inv;   // vs1
        o[4] = dn;

        atom_add_release(&g_count, 1u);   // release scratch into L2, no L1 flush
    }
}

extern "C" void kernel_launch(void* const* d_in, const int* in_sizes, int n_in,
                              void* d_out, int out_size)
{
    const float4* x = (const float4*)d_in[0];
    float* out = (float*)d_out;
    int B = in_sizes[0] / (N_PHAL * RES * RES * 5);   // 256
    int total_chunks = B * N_PHAL;                    // 5120

    float* scratch;
    cudaGetSymbolAddress((void**)&scratch, g_scratch);

    fused_kernel<<<total_chunks + 1, THREADS>>>(x, scratch, out, total_chunks);
}

// round 17
// speedup vs baseline: 1.4788x; 1.4788x over previous
#include <cuda_runtime.h>
#include <cstdint>

#define RES      64
#define N_PHAL   20
#define MAX_B    256

constexpr int F4_PER_CHUNK = RES * RES * 5 / 4;   // 5120 float4 per (b,p)
constexpr int NSUB         = 4;                   // subtiles per chunk
constexpr int SUB_F4       = F4_PER_CHUNK / NSUB; // 1280 float4 = 20 KB
constexpr int SUB_POS      = SUB_F4 * 4 / 5;      // 1024 positions
constexpr int THREADS      = 256;

// Scratch: per (b,p): vf0, vf1, vs0, vs1, den
__device__ float g_scratch[MAX_B * N_PHAL * 5];

__device__ __forceinline__ float warp_red(float v) {
    #pragma unroll
    for (int o = 16; o > 0; o >>= 1)
        v += __shfl_down_sync(0xffffffffu, v, o);
    return v;
}

// L2 evict-first policy (the R14 win) applied to cp.async staging.
__device__ __forceinline__ unsigned long long make_evict_first_policy() {
    unsigned long long p;
    asm("createpolicy.fractional.L2::evict_first.b64 %0, 1.0;" : "=l"(p));
    return p;
}
__device__ __forceinline__ void cp_async16_ef(unsigned int dst_smem,
                                              const void* src,
                                              unsigned long long pol) {
    asm volatile("cp.async.cg.shared.global.L2::cache_hint [%0], [%1], 16, %2;"
                 :: "r"(dst_smem), "l"(src), "l"(pol) : "memory");
}
__device__ __forceinline__ void cp_commit() {
    asm volatile("cp.async.commit_group;\n" ::: "memory");
}
template <int N>
__device__ __forceinline__ void cp_wait() {
    asm volatile("cp.async.wait_group %0;\n" :: "n"(N) : "memory");
}

// One block per (b,p) chunk: double-buffered cp.async pipeline (continuous
// memory issue) + evict-first L2 policy (the R14 discovery). Reduce ONLY —
// fusing anything into this kernel poisons its register allocation (R11-R16).
__global__ __launch_bounds__(THREADS, 4) void reduce_kernel(
    const float4* __restrict__ x, float* __restrict__ scratch)
{
    __shared__ float4 buf[2][SUB_F4];     // 2 x 20 KB double buffer
    __shared__ float  red[8][7];

    const int chunk = blockIdx.x;         // b * N_PHAL + p
    const float4* base = x + (size_t)chunk * F4_PER_CHUNK;
    const int t = threadIdx.x;

    const unsigned long long pol = make_evict_first_policy();

    float A = 0.f, Bm = 0.f, C = 0.f, D = 0.f, E = 0.f, F = 0.f, den = 0.f;

    unsigned int sb0 = (unsigned int)__cvta_generic_to_shared(&buf[0][t]);
    unsigned int sb1 = (unsigned int)__cvta_generic_to_shared(&buf[1][t]);

    // ---- prologue: issue subtiles 0 and 1 ----
    #pragma unroll
    for (int k = 0; k < 5; ++k)
        cp_async16_ef(sb0 + k * THREADS * 16, base + k * THREADS + t, pol);
    cp_commit();
    #pragma unroll
    for (int k = 0; k < 5; ++k)
        cp_async16_ef(sb1 + k * THREADS * 16, base + SUB_F4 + k * THREADS + t, pol);
    cp_commit();

    #pragma unroll
    for (int s = 0; s < NSUB; ++s) {
        cp_wait<1>();                     // subtile s landed (next in flight)
        __syncthreads();

        const float4* bc = buf[s & 1];
        // 5 x LDS.128 at 80B lane stride: conflict-free
        float4 v0 = bc[t * 5 + 0];
        float4 v1 = bc[t * 5 + 1];
        float4 v2 = bc[t * 5 + 2];
        float4 v3 = bc[t * 5 + 3];
        float4 v4 = bc[t * 5 + 4];

        int pos0 = s * SUB_POS + t * 4;   // first global position of group
        float fi  = (float)(pos0 >> 6);   // row (4 | 64 -> same for group)
        float fj0 = (float)(pos0 & 63);   // first column

        // p0: f0=v0.x f1=v0.y m=v0.z d0=v0.w d1=v1.x
        { float m = v0.z, am = fabsf(m), sc = m * am;
          float t0 = sc * v0.x, t1 = sc * v0.y;
          A  = fmaf(t1, v0.w, A);  Bm = fmaf(t0, v0.w, Bm);
          C  = fmaf(t1, v1.x, C);  D  = fmaf(t0, v1.x, D);
          E  = fmaf(am, fi, E);    F  = fmaf(am, fj0, F);
          den += am; }
        // p1: f0=v1.y f1=v1.z m=v1.w d0=v2.x d1=v2.y
        { float m = v1.w, am = fabsf(m), sc = m * am;
          float t0 = sc * v1.y, t1 = sc * v1.z;
          A  = fmaf(t1, v2.x, A);  Bm = fmaf(t0, v2.x, Bm);
          C  = fmaf(t1, v2.y, C);  D  = fmaf(t0, v2.y, D);
          E  = fmaf(am, fi, E);    F  = fmaf(am, fj0 + 1.f, F);
          den += am; }
        // p2: f0=v2.z f1=v2.w m=v3.x d0=v3.y d1=v3.z
        { float m = v3.x, am = fabsf(m), sc = m * am;
          float t0 = sc * v2.z, t1 = sc * v2.w;
          A  = fmaf(t1, v3.y, A);  Bm = fmaf(t0, v3.y, Bm);
          C  = fmaf(t1, v3.z, C);  D  = fmaf(t0, v3.z, D);
          E  = fmaf(am, fi, E);    F  = fmaf(am, fj0 + 2.f, F);
          den += am; }
        // p3: f0=v3.w f1=v4.x m=v4.y d0=v4.z d1=v4.w
        { float m = v4.y, am = fabsf(m), sc = m * am;
          float t0 = sc * v3.w, t1 = sc * v4.x;
          A  = fmaf(t1, v4.z, A);  Bm = fmaf(t0, v4.z, Bm);
          C  = fmaf(t1, v4.w, C);  D  = fmaf(t0, v4.w, D);
          E  = fmaf(am, fi, E);    F  = fmaf(am, fj0 + 3.f, F);
          den += am; }

        __syncthreads();                  // all threads done reading buf[s&1]
        if (s + 2 < NSUB) {               // refill the buffer just freed
            unsigned int sb = (s & 1) ? sb1 : sb0;
            const float4* nb = base + (s + 2) * SUB_F4;
            #pragma unroll
            for (int k = 0; k < 5; ++k)
                cp_async16_ef(sb + k * THREADS * 16, nb + k * THREADS + t, pol);
        }
        cp_commit();                      // commit (possibly empty) to keep count
    }

    // ---- block reduction of 7 accumulators ----
    A = warp_red(A);  Bm = warp_red(Bm); C = warp_red(C); D = warp_red(D);
    E = warp_red(E);  F  = warp_red(F);  den = warp_red(den);

    int wid = t >> 5, lane = t & 31;
    if (lane == 0) {
        red[wid][0] = A;  red[wid][1] = Bm; red[wid][2] = C;
        red[wid][3] = D;  red[wid][4] = E;  red[wid][5] = F;
        red[wid][6] = den;
    }
    __syncthreads();

    if (t == 0) {
        float a = 0.f, b = 0.f, c = 0.f, d = 0.f, e = 0.f, f = 0.f, dn = 0.f;
        #pragma unroll
        for (int w = 0; w < 8; ++w) {
            a += red[w][0]; b += red[w][1]; c += red[w][2];
            d += red[w][3]; e += red[w][4]; f += red[w][5];
            dn += red[w][6];
        }
        float inv = 1.f / ((dn == 0.f) ? 1.f : dn);
        float* o = scratch + (size_t)chunk * 5;
        o[0] = (a + e) * inv;   // vf0
        o[1] = (f - b) * inv;   // vf1
        o[2] = (e - c) * inv;   // vs0
        o[3] = (d + f) * inv;   // vs1
        o[4] = dn;
    }
}

// Assemble (B, 21, 2) keypoints. PDL: resident early, runs on completion trigger.
__global__ void finalize_kernel(const float* __restrict__ scratch,
                                float* __restrict__ out, int total)
{
#if __CUDA_ARCH__ >= 900
    cudaGridDependencySynchronize();     // wait for reduce_kernel completion
#endif
    int o = blockIdx.x * blockDim.x + threadIdx.x;
    if (o >= total) return;
    int c = o & 1;
    int r = (o >> 1) % 21;
    int b = o / 42;
    const float* s = scratch + (size_t)b * N_PHAL * 5;

    float val;
    if (r == 0) {
        float acc = 0.f;
        #pragma unroll
        for (int k = 0; k < 5; ++k) {
            int p = 4 * k;
            float dn = s[p * 5 + 4];
            float vf = s[p * 5 + c];
            acc += (dn != 0.f) ? vf : 0.f;
        }
        val = acc * 0.2f;
    } else {
        int q  = r;                 // 1..20
        int iq = (q - 1) >> 2;
        int pq = 8 * iq + 4 - q;    // = 4*iq + j_q
        int jq = pq - 4 * iq;
        int pn = min(pq + 1, N_PHAL - 1);
        float vs = s[pq * 5 + 2 + c];
        if (jq == 3) val = vs;                              // tip
        else         val = 0.5f * (vs + s[pn * 5 + c]);
    }
    out[o] = val;
}

extern "C" void kernel_launch(void* const* d_in, const int* in_sizes, int n_in,
                              void* d_out, int out_size)
{
    const float4* x = (const float4*)d_in[0];
    float* out = (float*)d_out;
    int B = in_sizes[0] / (N_PHAL * RES * RES * 5);   // 256

    float* scratch;
    cudaGetSymbolAddress((void**)&scratch, g_scratch);

    reduce_kernel<<<B * N_PHAL, THREADS>>>(x, scratch);

    int total = B * 21 * 2;
    cudaLaunchConfig_t cfg = {};
    cfg.gridDim  = dim3((total + 255) / 256, 1, 1);
    cfg.blockDim = dim3(256, 1, 1);
    cfg.dynamicSmemBytes = 0;
    cfg.stream = 0;
    cudaLaunchAttribute attr[1];
    attr[0].id = cudaLaunchAttributeProgrammaticStreamSerialization;
    attr[0].val.programmaticStreamSerializationAllowed = 1;
    cfg.attrs = attr;
    cfg.numAttrs = 1;
    cudaLaunchKernelEx(&cfg, finalize_kernel, (const float*)scratch, out, total);
}